// round 15
// baseline (speedup 1.0000x reference)
#include <cuda_runtime.h>
#include <cuda_bf16.h>
#include <cstdint>

// GIN 2-layer GNN for GB300 (sm_103a)
// Padded-CSR + fully fused per-layer kernel: warp-autonomous gather + 2-GEMM MLP.
#define N_NODES 50000
#define N_EDGES 800000
#define DI 64
#define DH 128
#define DO 64
#define CAP 128                               // padded slots per node

// Scratch
__device__ float4 g_hmid[N_NODES * DH / 4];   // layer-1 output (25.6 MB)
__device__ int    g_deg[N_NODES];
__device__ int    g_eid[N_NODES * CAP];       // src ids, padded (25.6 MB)
__device__ int    g_is32;

// ---------------------------------------------------------------------------
__global__ void init_kernel() {
    int i = blockIdx.x * blockDim.x + threadIdx.x;
    if (i == 0) g_is32 = 0;
    if (i < N_NODES) g_deg[i] = 0;
}

__global__ void detect_kernel(const void* ei) {
    const long long* e64 = (const long long*)ei;
    int i = blockIdx.x * blockDim.x + threadIdx.x;
    if (i < N_EDGES) {
        long long v = e64[i];
        if (v < 0 || v >= N_NODES) g_is32 = 1;
    }
}

__device__ __forceinline__ int edge_val(const void* ei, int idx) {
    if (g_is32) return ((const int*)ei)[idx];
    return (int)((const long long*)ei)[idx];
}

__global__ void fill_kernel(const void* __restrict__ ei) {
    int e = blockIdx.x * blockDim.x + threadIdx.x;
    if (e >= N_EDGES) return;
    int s = edge_val(ei, e);
    int d = edge_val(ei, N_EDGES + e);
    if ((unsigned)s >= N_NODES || (unsigned)d >= N_NODES) return;
    int pos = atomicAdd(&g_deg[d], 1);
    if (pos < CAP) g_eid[d * CAP + pos] = s;
}

// ---------------------------------------------------------------------------
// Packed f32x2 helpers
// ---------------------------------------------------------------------------
__device__ __forceinline__ unsigned long long ffma2(unsigned long long a,
                                                    unsigned long long b,
                                                    unsigned long long c) {
    unsigned long long d;
    asm("fma.rn.f32x2 %0, %1, %2, %3;" : "=l"(d) : "l"(a), "l"(b), "l"(c));
    return d;
}
__device__ __forceinline__ unsigned long long dup2(float x) {
    unsigned long long d;
    unsigned int u = __float_as_uint(x);
    asm("mov.b64 %0, {%1, %1};" : "=l"(d) : "r"(u));
    return d;
}
__device__ __forceinline__ void unpack2(unsigned long long v, float& lo, float& hi) {
    unsigned int a, b;
    asm("mov.b64 {%0, %1}, %2;" : "=r"(a), "=r"(b) : "l"(v));
    lo = __uint_as_float(a); hi = __uint_as_float(b);
}
// volatile + memory clobber: never hoisted/CSE'd across the smem stores.
__device__ __forceinline__ void lds_v2b64(uint32_t addr,
                                          unsigned long long& a,
                                          unsigned long long& b) {
    asm volatile("ld.shared.v2.b64 {%0, %1}, [%2];"
                 : "=l"(a), "=l"(b) : "r"(addr) : "memory");
}

// ---------------------------------------------------------------------------
// Per-row gather into registers: acc = feat[row] + sum_{s in N(row)} feat[s]
// Warp-collective; lane holds feat cols [lane*V, lane*V+V).
// ---------------------------------------------------------------------------
template <int D>
__device__ __forceinline__ void gather_row(const float* __restrict__ feat,
                                           int row, int lane, float* acc) {
    constexpr int V = D / 32;
#pragma unroll
    for (int v = 0; v < V; v++) acc[v] = 0.f;
    if (row >= N_NODES) return;
    {
        const float* p = feat + (long long)row * D + lane * V;
        if (V == 4) {
            float4 f = __ldg(reinterpret_cast<const float4*>(p));
            acc[0] = f.x; acc[1] = f.y;
            acc[V > 2 ? 2 : 0] = f.z; acc[V > 3 ? 3 : 0] = f.w;
        } else {
            float2 f = __ldg(reinterpret_cast<const float2*>(p));
            acc[0] = f.x; acc[1] = f.y;
        }
    }
    const int deg = min(g_deg[row], CAP);
    const int base = row * CAP;
    for (int b = 0; b < deg; b += 32) {
        int my = (b + lane < deg) ? g_eid[base + b + lane] : 0;
        int n = min(32, deg - b);
        for (int j = 0; j < n; j++) {
            int s = __shfl_sync(0xffffffffu, my, j);
            const float* p = feat + (long long)s * D + lane * V;
            if (V == 4) {
                float4 f = __ldg(reinterpret_cast<const float4*>(p));
                acc[0] += f.x; acc[1] += f.y;
                acc[V > 2 ? 2 : 0] += f.z; acc[V > 3 ? 3 : 0] += f.w;
            } else {
                float2 f = __ldg(reinterpret_cast<const float2*>(p));
                acc[0] += f.x; acc[1] += f.y;
            }
        }
    }
}

// ---------------------------------------------------------------------------
// Fused layer kernel: per-warp gather + 2-linear MLP on f32x2 row-pairs.
// 512 threads, 1 block/SM, RT=128 rows/tile; warp g owns pairs q0..q0+3.
// NO block barriers inside the tile loop — warps touch only their own rows;
// sRow and sMid are disjoint regions.
// ---------------------------------------------------------------------------
template <int DIN, int DOUT>
__global__ void __launch_bounds__(512, 1)
fused_kernel(const float* __restrict__ feat,
             const float* __restrict__ Wa,
             const float* __restrict__ ba,
             const float* __restrict__ Wb,
             const float* __restrict__ bb,
             float* __restrict__ out) {
    constexpr int P  = 4;                 // row pairs per warp
    constexpr int RT = 128;               // rows per tile
    constexpr int V  = DIN / 32;          // gather floats per lane per row
    constexpr int C2 = DOUT / 32;         // phase-2 cols per thread

    extern __shared__ float sm[];
    float* sWa  = sm;                     // DIN * 128
    float* sWb  = sWa + DIN * 128;        // 128 * DOUT
    float* sRow = sWb + 128 * DOUT;       // RT * DIN   (pair-packed rows)
    float* sMid = sRow + RT * DIN;        // RT * 128   (pair-packed mid)

    const int t = threadIdx.x;            // 0..511
    const int g = t >> 5;                 // warp 0..15
    const int c = t & 31;                 // lane
    const int q0 = g * P;

    for (int i = t; i < DIN * 128 / 4; i += 512)
        reinterpret_cast<float4*>(sWa)[i] = reinterpret_cast<const float4*>(Wa)[i];
    for (int i = t; i < 128 * DOUT / 4; i += 512)
        reinterpret_cast<float4*>(sWb)[i] = reinterpret_cast<const float4*>(Wb)[i];
    __syncthreads();

    // Phase-1 bias (cols 4c..4c+3)
    const float4 baq = __ldg(reinterpret_cast<const float4*>(ba + 4 * c));
    unsigned long long baD[4];
    baD[0] = dup2(baq.x); baD[1] = dup2(baq.y);
    baD[2] = dup2(baq.z); baD[3] = dup2(baq.w);

    // Phase-2 bias (cols C2*c .. C2*c+C2-1)
    unsigned long long bbD[C2];
#pragma unroll
    for (int j = 0; j < C2; j++) bbD[j] = dup2(__ldg(bb + C2 * c + j));

    const uint32_t sRowAddr = (uint32_t)__cvta_generic_to_shared(sRow);
    const uint32_t sMidAddr = (uint32_t)__cvta_generic_to_shared(sMid);

    const int ntiles = (N_NODES + RT - 1) / RT;
    for (int tile = blockIdx.x; tile < ntiles; tile += gridDim.x) {
        const int r0 = tile * RT;

        // prev-iteration reads of sRow/sMid (all lanes) must complete
        __syncwarp();

        // ---- Gather own P row-pairs into sRow (pair-packed) ----
#pragma unroll
        for (int p = 0; p < P; p++) {
            const int rowE = r0 + 2 * (q0 + p);
            const int rowO = rowE + 1;
            float aE[V], aO[V];
            gather_row<DIN>(feat, rowE, c, aE);
            gather_row<DIN>(feat, rowO, c, aO);
            float* dst = &sRow[(q0 + p) * (DIN * 2) + 2 * (c * V)];
#pragma unroll
            for (int v = 0; v < V; v += 2) {
                float4 st = make_float4(aE[v], aO[v], aE[v + 1], aO[v + 1]);
                *reinterpret_cast<float4*>(dst + 2 * v) = st;
            }
        }
        __syncwarp();

        // ---- Phase 1: mid = relu(rows @ Wa + ba), 128 cols, 4/thread ----
        unsigned long long acc[P][4];
#pragma unroll
        for (int p = 0; p < P; p++)
#pragma unroll
            for (int j = 0; j < 4; j++) acc[p][j] = baD[j];

#pragma unroll
        for (int k = 0; k < DIN; k += 2) {
            float4 w0 = *reinterpret_cast<const float4*>(&sWa[k * 128 + 4 * c]);
            float4 w1 = *reinterpret_cast<const float4*>(&sWa[(k + 1) * 128 + 4 * c]);
            unsigned long long w0d[4] = {dup2(w0.x), dup2(w0.y), dup2(w0.z), dup2(w0.w)};
            unsigned long long w1d[4] = {dup2(w1.x), dup2(w1.y), dup2(w1.z), dup2(w1.w)};
#pragma unroll
            for (int p = 0; p < P; p++) {
                unsigned long long vk, vk1;
                lds_v2b64(sRowAddr + ((q0 + p) * (DIN * 2) + k * 2) * 4, vk, vk1);
#pragma unroll
                for (int j = 0; j < 4; j++) {
                    acc[p][j] = ffma2(w0d[j], vk, acc[p][j]);
                    acc[p][j] = ffma2(w1d[j], vk1, acc[p][j]);
                }
            }
        }

        // relu + store mid pair-packed into sMid
#pragma unroll
        for (int p = 0; p < P; p++) {
            float lo0, hi0, lo1, hi1, lo2, hi2, lo3, hi3;
            unpack2(acc[p][0], lo0, hi0);
            unpack2(acc[p][1], lo1, hi1);
            unpack2(acc[p][2], lo2, hi2);
            unpack2(acc[p][3], lo3, hi3);
            float4 m0, m1;
            m0.x = fmaxf(lo0, 0.f); m0.y = fmaxf(hi0, 0.f);
            m0.z = fmaxf(lo1, 0.f); m0.w = fmaxf(hi1, 0.f);
            m1.x = fmaxf(lo2, 0.f); m1.y = fmaxf(hi2, 0.f);
            m1.z = fmaxf(lo3, 0.f); m1.w = fmaxf(hi3, 0.f);
            float* dst = &sMid[(q0 + p) * 256 + 8 * c];
            *reinterpret_cast<float4*>(dst)     = m0;
            *reinterpret_cast<float4*>(dst + 4) = m1;
        }
        __syncwarp();

        // ---- Phase 2: out = relu(mid @ Wb + bb), DOUT cols, C2/thread ----
        unsigned long long acc2[P][C2];
#pragma unroll
        for (int p = 0; p < P; p++)
#pragma unroll
            for (int j = 0; j < C2; j++) acc2[p][j] = bbD[j];

#pragma unroll
        for (int k = 0; k < 128; k += 2) {
            unsigned long long w0d[C2], w1d[C2];
            if (C2 == 4) {
                float4 w0 = *reinterpret_cast<const float4*>(&sWb[k * DOUT + 4 * c]);
                float4 w1 = *reinterpret_cast<const float4*>(&sWb[(k + 1) * DOUT + 4 * c]);
                w0d[0] = dup2(w0.x); w0d[1] = dup2(w0.y);
                w0d[C2 > 2 ? 2 : 0] = dup2(w0.z); w0d[C2 > 3 ? 3 : 0] = dup2(w0.w);
                w1d[0] = dup2(w1.x); w1d[1] = dup2(w1.y);
                w1d[C2 > 2 ? 2 : 0] = dup2(w1.z); w1d[C2 > 3 ? 3 : 0] = dup2(w1.w);
            } else {
                float2 w0 = *reinterpret_cast<const float2*>(&sWb[k * DOUT + 2 * c]);
                float2 w1 = *reinterpret_cast<const float2*>(&sWb[(k + 1) * DOUT + 2 * c]);
                w0d[0] = dup2(w0.x); w0d[1] = dup2(w0.y);
                w1d[0] = dup2(w1.x); w1d[1] = dup2(w1.y);
            }
#pragma unroll
            for (int p = 0; p < P; p++) {
                unsigned long long vk, vk1;
                lds_v2b64(sMidAddr + ((q0 + p) * 256 + k * 2) * 4, vk, vk1);
#pragma unroll
                for (int j = 0; j < C2; j++) {
                    acc2[p][j] = ffma2(w0d[j], vk, acc2[p][j]);
                    acc2[p][j] = ffma2(w1d[j], vk1, acc2[p][j]);
                }
            }
        }

        // relu + store to global
#pragma unroll
        for (int p = 0; p < P; p++) {
            float ev[C2], ov[C2];
#pragma unroll
            for (int j = 0; j < C2; j++) {
                float lo, hi;
                unpack2(acc2[p][j], lo, hi);
                ev[j] = fmaxf(lo, 0.f);
                ov[j] = fmaxf(hi, 0.f);
            }
            int rowE = r0 + 2 * (q0 + p);
            int rowO = rowE + 1;
            if (C2 == 4) {
                if (rowE < N_NODES)
                    *reinterpret_cast<float4*>(&out[(long long)rowE * DOUT + 4 * c]) =
                        make_float4(ev[0], ev[1], ev[C2 > 2 ? 2 : 0], ev[C2 > 3 ? 3 : 0]);
                if (rowO < N_NODES)
                    *reinterpret_cast<float4*>(&out[(long long)rowO * DOUT + 4 * c]) =
                        make_float4(ov[0], ov[1], ov[C2 > 2 ? 2 : 0], ov[C2 > 3 ? 3 : 0]);
            } else {
                if (rowE < N_NODES)
                    *reinterpret_cast<float2*>(&out[(long long)rowE * DOUT + 2 * c]) =
                        make_float2(ev[0], ev[1]);
                if (rowO < N_NODES)
                    *reinterpret_cast<float2*>(&out[(long long)rowO * DOUT + 2 * c]) =
                        make_float2(ov[0], ov[1]);
            }
        }
    }
}

// ---------------------------------------------------------------------------
extern "C" void kernel_launch(void* const* d_in, const int* in_sizes, int n_in,
                              void* d_out, int out_size) {
    const float* x   = (const float*)d_in[0];
    const void*  ei  = d_in[1];
    const float* W1a = (const float*)d_in[2];
    const float* b1a = (const float*)d_in[3];
    const float* W1b = (const float*)d_in[4];
    const float* b1b = (const float*)d_in[5];
    const float* W2a = (const float*)d_in[6];
    const float* b2a = (const float*)d_in[7];
    const float* W2b = (const float*)d_in[8];
    const float* b2b = (const float*)d_in[9];
    float*       out = (float*)d_out;

    float* hmid;
    cudaGetSymbolAddress((void**)&hmid, g_hmid);

    const int RT = 128;
    // floats: Wa + Wb + rows + mid
    const int SMEM1 = (DI * 128 + 128 * DH + RT * DI + RT * 128) * 4;  // 192 KB
    const int SMEM2 = (DH * 128 + 128 * DO + RT * DH + RT * 128) * 4;  // 224 KB
    cudaFuncSetAttribute(fused_kernel<DI, DH>,
                         cudaFuncAttributeMaxDynamicSharedMemorySize, SMEM1);
    cudaFuncSetAttribute(fused_kernel<DH, DO>,
                         cudaFuncAttributeMaxDynamicSharedMemorySize, SMEM2);

    // Padded-CSR build
    init_kernel<<<(N_NODES + 255) / 256, 256>>>();
    detect_kernel<<<(N_EDGES + 255) / 256, 256>>>(ei);
    fill_kernel<<<(N_EDGES + 255) / 256, 256>>>(ei);

    // Layer 1: gather(x) + MLP -> hmid
    fused_kernel<DI, DH><<<148, 512, SMEM1>>>(x, W1a, b1a, W1b, b1b, hmid);
    // Layer 2: gather(hmid) + MLP -> out
    fused_kernel<DH, DO><<<148, 512, SMEM2>>>(hmid, W2a, b2a, W2b, b2b, out);
}

// round 16
// speedup vs baseline: 1.2126x; 1.2126x over previous
#include <cuda_runtime.h>
#include <cuda_fp16.h>
#include <cstdint>

// GIN 2-layer GNN for GB300 (sm_103a)
// Padded-CSR gather + big-tile FFMA2 MLP (R12 architecture), fp16 hmid.
#define N_NODES 50000
#define N_EDGES 800000
#define DI 64
#define DH 128
#define DO 64
#define CAP 128                               // padded slots per node

// Scratch (device globals)
__device__ float4 g_h1[N_NODES * DI / 4];     // x + agg1        (12.8 MB)
__device__ uint2  g_hmid[N_NODES * DH / 4];   // mlp1 out, fp16  (12.8 MB)
__device__ float4 g_h2[N_NODES * DH / 4];     // hmid + agg2     (25.6 MB)
__device__ int    g_deg[N_NODES];
__device__ int    g_eid[N_NODES * CAP];       // src ids, padded (25.6 MB)
__device__ int    g_is32;

// ---------------------------------------------------------------------------
__global__ void init_kernel() {
    int i = blockIdx.x * blockDim.x + threadIdx.x;
    if (i == 0) g_is32 = 0;
    if (i < N_NODES) g_deg[i] = 0;
}

__global__ void detect_kernel(const void* ei) {
    const long long* e64 = (const long long*)ei;
    int i = blockIdx.x * blockDim.x + threadIdx.x;
    if (i < N_EDGES) {
        long long v = e64[i];
        if (v < 0 || v >= N_NODES) g_is32 = 1;
    }
}

__device__ __forceinline__ int edge_val(const void* ei, int idx) {
    if (g_is32) return ((const int*)ei)[idx];
    return (int)((const long long*)ei)[idx];
}

__global__ void fill_kernel(const void* __restrict__ ei) {
    int e = blockIdx.x * blockDim.x + threadIdx.x;
    if (e >= N_EDGES) return;
    int s = edge_val(ei, e);
    int d = edge_val(ei, N_EDGES + e);
    if ((unsigned)s >= N_NODES || (unsigned)d >= N_NODES) return;
    int pos = atomicAdd(&g_deg[d], 1);
    if (pos < CAP) g_eid[d * CAP + pos] = s;
}

// ---------------------------------------------------------------------------
// Gather fused with GIN self-add: outh = feat[node] + sum feat[src]. Warp/node.
// HALFIN: feat is fp16 (layer-2 path); accumulate fp32.
// ---------------------------------------------------------------------------
template <int D, bool HALFIN>
__global__ void gather_kernel(const void* __restrict__ feat_,
                              float* __restrict__ outh) {
    constexpr int V = D / 32;                  // elems per lane (2 or 4)
    int warp = (blockIdx.x * blockDim.x + threadIdx.x) >> 5;
    int lane = threadIdx.x & 31;
    if (warp >= N_NODES) return;
    const int node = warp;
    const int deg = min(g_deg[node], CAP);
    const int base = node * CAP;

    float acc[V];
#pragma unroll
    for (int v = 0; v < V; v++) acc[v] = 0.f;

    // self
    if constexpr (HALFIN) {
        const __half* feat = (const __half*)feat_;
        uint2 u = __ldg(reinterpret_cast<const uint2*>(
            feat + (long long)node * D + lane * V));
        __half2 h0 = *reinterpret_cast<__half2*>(&u.x);
        __half2 h1 = *reinterpret_cast<__half2*>(&u.y);
        float2 f0 = __half22float2(h0), f1 = __half22float2(h1);
        acc[0] = f0.x; acc[1] = f0.y;
        acc[V > 2 ? 2 : 0] = f1.x; acc[V > 3 ? 3 : 0] = f1.y;
    } else {
        const float* feat = (const float*)feat_;
        const float* p = feat + (long long)node * D + lane * V;
        if (V == 4) {
            float4 f = __ldg(reinterpret_cast<const float4*>(p));
            acc[0] = f.x; acc[1] = f.y;
            acc[V > 2 ? 2 : 0] = f.z; acc[V > 3 ? 3 : 0] = f.w;
        } else {
            float2 f = __ldg(reinterpret_cast<const float2*>(p));
            acc[0] = f.x; acc[1] = f.y;
        }
    }

    for (int b = 0; b < deg; b += 32) {
        int my = (b + lane < deg) ? g_eid[base + b + lane] : 0;
        int n = min(32, deg - b);
        for (int j = 0; j < n; j++) {
            int s = __shfl_sync(0xffffffffu, my, j);
            if constexpr (HALFIN) {
                const __half* feat = (const __half*)feat_;
                uint2 u = __ldg(reinterpret_cast<const uint2*>(
                    feat + (long long)s * D + lane * V));
                __half2 h0 = *reinterpret_cast<__half2*>(&u.x);
                __half2 h1 = *reinterpret_cast<__half2*>(&u.y);
                float2 f0 = __half22float2(h0), f1 = __half22float2(h1);
                acc[0] += f0.x; acc[1] += f0.y;
                acc[V > 2 ? 2 : 0] += f1.x; acc[V > 3 ? 3 : 0] += f1.y;
            } else {
                const float* feat = (const float*)feat_;
                const float* p = feat + (long long)s * D + lane * V;
                if (V == 4) {
                    float4 f = __ldg(reinterpret_cast<const float4*>(p));
                    acc[0] += f.x; acc[1] += f.y;
                    acc[V > 2 ? 2 : 0] += f.z; acc[V > 3 ? 3 : 0] += f.w;
                } else {
                    float2 f = __ldg(reinterpret_cast<const float2*>(p));
                    acc[0] += f.x; acc[1] += f.y;
                }
            }
        }
    }
    float* q = outh + (long long)node * D + lane * V;
#pragma unroll
    for (int v = 0; v < V; v++) q[v] = acc[v];
}

// ---------------------------------------------------------------------------
// Packed f32x2 helpers
// ---------------------------------------------------------------------------
__device__ __forceinline__ unsigned long long ffma2(unsigned long long a,
                                                    unsigned long long b,
                                                    unsigned long long c) {
    unsigned long long d;
    asm("fma.rn.f32x2 %0, %1, %2, %3;" : "=l"(d) : "l"(a), "l"(b), "l"(c));
    return d;
}
__device__ __forceinline__ unsigned long long dup2(float x) {
    unsigned long long d;
    unsigned int u = __float_as_uint(x);
    asm("mov.b64 %0, {%1, %1};" : "=l"(d) : "r"(u));
    return d;
}
__device__ __forceinline__ void unpack2(unsigned long long v, float& lo, float& hi) {
    unsigned int a, b;
    asm("mov.b64 {%0, %1}, %2;" : "=r"(a), "=r"(b) : "l"(v));
    lo = __uint_as_float(a); hi = __uint_as_float(b);
}
// volatile + memory clobber: never hoisted/CSE'd across the smem stores.
__device__ __forceinline__ void lds_v2b64(uint32_t addr,
                                          unsigned long long& a,
                                          unsigned long long& b) {
    asm volatile("ld.shared.v2.b64 {%0, %1}, [%2];"
                 : "=l"(a), "=l"(b) : "r"(addr) : "memory");
}

// ---------------------------------------------------------------------------
// Big-tile fused 2-linear MLP (R12). 512 threads, 1 block/SM, RT=128 rows/tile.
// 16 warps = 16 row-groups (P=4 pairs); each thread owns 4 phase-1 cols.
// OUTHALF: epilogue stores fp16 (layer-1 -> hmid).
// ---------------------------------------------------------------------------
template <int DIN, int DOUT, bool OUTHALF>
__global__ void __launch_bounds__(512, 1)
mlp_kernel(const float* __restrict__ in,
           const float* __restrict__ Wa,
           const float* __restrict__ ba,
           const float* __restrict__ Wb,
           const float* __restrict__ bb,
           void* __restrict__ out_) {
    constexpr int P  = 4;
    constexpr int RT = 128;
    constexpr int C2 = DOUT / 32;         // 4 or 2

    extern __shared__ float sm[];
    float* sWa  = sm;                     // DIN * 128
    float* sWb  = sWa + DIN * 128;        // 128 * DOUT
    float* sBuf = sWb + 128 * DOUT;       // RT * 128 (pair-packed rows / mid)

    const int t = threadIdx.x;
    const int g = t >> 5;
    const int c = t & 31;
    const int q0 = g * P;

    for (int i = t; i < DIN * 128 / 4; i += 512)
        reinterpret_cast<float4*>(sWa)[i] = reinterpret_cast<const float4*>(Wa)[i];
    for (int i = t; i < 128 * DOUT / 4; i += 512)
        reinterpret_cast<float4*>(sWb)[i] = reinterpret_cast<const float4*>(Wb)[i];
    __syncthreads();

    const float4 baq = __ldg(reinterpret_cast<const float4*>(ba + 4 * c));
    unsigned long long baD[4];
    baD[0] = dup2(baq.x); baD[1] = dup2(baq.y);
    baD[2] = dup2(baq.z); baD[3] = dup2(baq.w);

    unsigned long long bbD[C2];
#pragma unroll
    for (int j = 0; j < C2; j++) bbD[j] = dup2(__ldg(bb + C2 * c + j));

    const uint32_t sBufAddr = (uint32_t)__cvta_generic_to_shared(sBuf);

    const int ntiles = (N_NODES + RT - 1) / RT;
    for (int tile = blockIdx.x; tile < ntiles; tile += gridDim.x) {
        const int r0 = tile * RT;

        // Stage RT rows pair-packed: sBuf[q*(DIN*2) + k*2 + (r&1)]
        for (int i = t; i < RT * DIN; i += 512) {
            int r = i / DIN, k = i - r * DIN;
            int row = r0 + r;
            float v = 0.f;
            if (row < N_NODES) v = in[(long long)row * DIN + k];
            sBuf[(r >> 1) * (DIN * 2) + k * 2 + (r & 1)] = v;
        }
        __syncthreads();

        // ---- Phase 1: mid = relu(rows @ Wa + ba), 128 cols, 4/thread ----
        unsigned long long acc[P][4];
#pragma unroll
        for (int p = 0; p < P; p++)
#pragma unroll
            for (int j = 0; j < 4; j++) acc[p][j] = baD[j];

#pragma unroll
        for (int k = 0; k < DIN; k += 2) {
            float4 w0 = *reinterpret_cast<const float4*>(&sWa[k * 128 + 4 * c]);
            float4 w1 = *reinterpret_cast<const float4*>(&sWa[(k + 1) * 128 + 4 * c]);
            unsigned long long w0d[4] = {dup2(w0.x), dup2(w0.y), dup2(w0.z), dup2(w0.w)};
            unsigned long long w1d[4] = {dup2(w1.x), dup2(w1.y), dup2(w1.z), dup2(w1.w)};
#pragma unroll
            for (int p = 0; p < P; p++) {
                unsigned long long vk, vk1;
                lds_v2b64(sBufAddr + ((q0 + p) * (DIN * 2) + k * 2) * 4, vk, vk1);
#pragma unroll
                for (int j = 0; j < 4; j++) {
                    acc[p][j] = ffma2(w0d[j], vk, acc[p][j]);
                    acc[p][j] = ffma2(w1d[j], vk1, acc[p][j]);
                }
            }
        }
        __syncthreads();   // done reading row data

        // relu + store mid pair-packed: sBuf[q*256 + col*2 + half]
#pragma unroll
        for (int p = 0; p < P; p++) {
            float lo0, hi0, lo1, hi1, lo2, hi2, lo3, hi3;
            unpack2(acc[p][0], lo0, hi0);
            unpack2(acc[p][1], lo1, hi1);
            unpack2(acc[p][2], lo2, hi2);
            unpack2(acc[p][3], lo3, hi3);
            float4 m0, m1;
            m0.x = fmaxf(lo0, 0.f); m0.y = fmaxf(hi0, 0.f);
            m0.z = fmaxf(lo1, 0.f); m0.w = fmaxf(hi1, 0.f);
            m1.x = fmaxf(lo2, 0.f); m1.y = fmaxf(hi2, 0.f);
            m1.z = fmaxf(lo3, 0.f); m1.w = fmaxf(hi3, 0.f);
            float* dst = &sBuf[(q0 + p) * 256 + 8 * c];
            *reinterpret_cast<float4*>(dst)     = m0;
            *reinterpret_cast<float4*>(dst + 4) = m1;
        }
        __syncthreads();

        // ---- Phase 2: out = relu(mid @ Wb + bb), DOUT cols, C2/thread ----
        unsigned long long acc2[P][C2];
#pragma unroll
        for (int p = 0; p < P; p++)
#pragma unroll
            for (int j = 0; j < C2; j++) acc2[p][j] = bbD[j];

#pragma unroll
        for (int k = 0; k < 128; k += 2) {
            unsigned long long w0d[C2], w1d[C2];
            if (C2 == 4) {
                float4 w0 = *reinterpret_cast<const float4*>(&sWb[k * DOUT + 4 * c]);
                float4 w1 = *reinterpret_cast<const float4*>(&sWb[(k + 1) * DOUT + 4 * c]);
                w0d[0] = dup2(w0.x); w0d[1] = dup2(w0.y);
                w0d[C2 > 2 ? 2 : 0] = dup2(w0.z); w0d[C2 > 3 ? 3 : 0] = dup2(w0.w);
                w1d[0] = dup2(w1.x); w1d[1] = dup2(w1.y);
                w1d[C2 > 2 ? 2 : 0] = dup2(w1.z); w1d[C2 > 3 ? 3 : 0] = dup2(w1.w);
            } else {
                float2 w0 = *reinterpret_cast<const float2*>(&sWb[k * DOUT + 2 * c]);
                float2 w1 = *reinterpret_cast<const float2*>(&sWb[(k + 1) * DOUT + 2 * c]);
                w0d[0] = dup2(w0.x); w0d[1] = dup2(w0.y);
                w1d[0] = dup2(w1.x); w1d[1] = dup2(w1.y);
            }
#pragma unroll
            for (int p = 0; p < P; p++) {
                unsigned long long vk, vk1;
                lds_v2b64(sBufAddr + ((q0 + p) * 256 + k * 2) * 4, vk, vk1);
#pragma unroll
                for (int j = 0; j < C2; j++) {
                    acc2[p][j] = ffma2(w0d[j], vk, acc2[p][j]);
                    acc2[p][j] = ffma2(w1d[j], vk1, acc2[p][j]);
                }
            }
        }

        // relu + store to global (fp32 or fp16)
#pragma unroll
        for (int p = 0; p < P; p++) {
            float ev[C2], ov[C2];
#pragma unroll
            for (int j = 0; j < C2; j++) {
                float lo, hi;
                unpack2(acc2[p][j], lo, hi);
                ev[j] = fmaxf(lo, 0.f);
                ov[j] = fmaxf(hi, 0.f);
            }
            int rowE = r0 + 2 * (q0 + p);
            int rowO = rowE + 1;
            if constexpr (OUTHALF) {
                __half* outH = (__half*)out_;
                union { __half2 h2v[2]; uint2 u; } pkE, pkO;
                pkE.h2v[0] = __floats2half2_rn(ev[0], ev[1]);
                pkE.h2v[1] = __floats2half2_rn(ev[C2 > 2 ? 2 : 0], ev[C2 > 3 ? 3 : 0]);
                pkO.h2v[0] = __floats2half2_rn(ov[0], ov[1]);
                pkO.h2v[1] = __floats2half2_rn(ov[C2 > 2 ? 2 : 0], ov[C2 > 3 ? 3 : 0]);
                if (rowE < N_NODES)
                    *reinterpret_cast<uint2*>(outH + (long long)rowE * DOUT + 4 * c) = pkE.u;
                if (rowO < N_NODES)
                    *reinterpret_cast<uint2*>(outH + (long long)rowO * DOUT + 4 * c) = pkO.u;
            } else {
                float* out = (float*)out_;
                if (C2 == 4) {
                    if (rowE < N_NODES)
                        *reinterpret_cast<float4*>(&out[(long long)rowE * DOUT + 4 * c]) =
                            make_float4(ev[0], ev[1], ev[C2 > 2 ? 2 : 0], ev[C2 > 3 ? 3 : 0]);
                    if (rowO < N_NODES)
                        *reinterpret_cast<float4*>(&out[(long long)rowO * DOUT + 4 * c]) =
                            make_float4(ov[0], ov[1], ov[C2 > 2 ? 2 : 0], ov[C2 > 3 ? 3 : 0]);
                } else {
                    if (rowE < N_NODES)
                        *reinterpret_cast<float2*>(&out[(long long)rowE * DOUT + 2 * c]) =
                            make_float2(ev[0], ev[1]);
                    if (rowO < N_NODES)
                        *reinterpret_cast<float2*>(&out[(long long)rowO * DOUT + 2 * c]) =
                            make_float2(ov[0], ov[1]);
                }
            }
        }
        __syncthreads();
    }
}

// ---------------------------------------------------------------------------
extern "C" void kernel_launch(void* const* d_in, const int* in_sizes, int n_in,
                              void* d_out, int out_size) {
    const float* x   = (const float*)d_in[0];
    const void*  ei  = d_in[1];
    const float* W1a = (const float*)d_in[2];
    const float* b1a = (const float*)d_in[3];
    const float* W1b = (const float*)d_in[4];
    const float* b1b = (const float*)d_in[5];
    const float* W2a = (const float*)d_in[6];
    const float* b2a = (const float*)d_in[7];
    const float* W2b = (const float*)d_in[8];
    const float* b2b = (const float*)d_in[9];
    float*       out = (float*)d_out;

    float *h1, *h2;
    void* hmid;
    cudaGetSymbolAddress((void**)&h1,   g_h1);
    cudaGetSymbolAddress(&hmid,         g_hmid);
    cudaGetSymbolAddress((void**)&h2,   g_h2);

    const int RT = 128;
    const int SMEM1 = (DI * 128 + 128 * DH + RT * 128) * 4;  // 160 KB
    const int SMEM2 = (DH * 128 + 128 * DO + RT * 128) * 4;  // 160 KB
    cudaFuncSetAttribute(mlp_kernel<DI, DH, true>,
                         cudaFuncAttributeMaxDynamicSharedMemorySize, SMEM1);
    cudaFuncSetAttribute(mlp_kernel<DH, DO, false>,
                         cudaFuncAttributeMaxDynamicSharedMemorySize, SMEM2);

    // Padded-CSR build
    init_kernel<<<(N_NODES + 255) / 256, 256>>>();
    detect_kernel<<<(N_EDGES + 255) / 256, 256>>>(ei);
    fill_kernel<<<(N_EDGES + 255) / 256, 256>>>(ei);

    // Layer 1: gather(x) fp32 -> h1 ; MLP -> hmid (fp16)
    gather_kernel<DI, false><<<(N_NODES * 32 + 255) / 256, 256>>>(x, h1);
    mlp_kernel<DI, DH, true><<<148, 512, SMEM1>>>(h1, W1a, b1a, W1b, b1b, hmid);
    // Layer 2: gather(hmid fp16) -> h2 fp32 ; MLP -> out fp32
    gather_kernel<DH, true><<<(N_NODES * 32 + 255) / 256, 256>>>(hmid, h2);
    mlp_kernel<DH, DO, false><<<148, 512, SMEM2>>>(h2, W2a, b2a, W2b, b2b, out);
}